// round 12
// baseline (speedup 1.0000x reference)
#include <cuda_runtime.h>
#include <cuda_bf16.h>
#include <math.h>

// ---------------------------------------------------------------------------
// Problem constants
// ---------------------------------------------------------------------------
#define BB    1024
#define TENC  128
#define TDEC  64
#define HH    128
#define FF    16
#define SS    8
#define HE    256
#define HD    132
#define SB    (SS*BB)
#define TT    (TENC+TDEC)
#define DEC_BASE 2080768    // 8*1024*127*2
#define ENC_SSTRIDE 260096  // 1024*127*2

typedef unsigned long long ull;

// ---------------------------------------------------------------------------
// Device scratch
// ---------------------------------------------------------------------------
__device__ __align__(128) float g_h0[2 * BB * HE];
__device__ __align__(128) float g_h1[2 * BB * HE];
__device__ __align__(128) float g_enc[TENC * BB * HH];
__device__ __align__(128) float g_last[BB * 2];
__device__ __align__(128) float g_dh0[2 * SB * HD];
__device__ __align__(128) float g_dh1[2 * SB * HD];
__device__ __align__(128) float g_dout[SB * 2];

// ---------------------------------------------------------------------------
// Helpers
// ---------------------------------------------------------------------------
__device__ __forceinline__ float sigm(float x) { return 1.f / (1.f + expf(-x)); }
__device__ __forceinline__ float softp(float x) {
    return fmaxf(x, 0.f) + log1pf(expf(-fabsf(x)));
}
__device__ __forceinline__ void fma2(ull &d, ull a, ull b) {
    asm("fma.rn.f32x2 %0, %1, %2, %0;" : "+l"(d) : "l"(a), "l"(b));
}
__device__ __forceinline__ float hsum2(ull v) {
    float lo = __uint_as_float((unsigned)(v & 0xffffffffull));
    float hi = __uint_as_float((unsigned)(v >> 32));
    return lo + hi;
}
__device__ __forceinline__ void cpa16(float* dst, const float* src) {
    unsigned sa = (unsigned)__cvta_generic_to_shared(dst);
    asm volatile("cp.async.cg.shared.global [%0], [%1], 16;\n" :: "r"(sa), "l"(src));
}
__device__ __forceinline__ void cpa_commit() { asm volatile("cp.async.commit_group;\n"); }
template<int N> __device__ __forceinline__ void cpa_wait() {
    asm volatile("cp.async.wait_group %0;\n" :: "n"(N));
}

// Chunking: chunks of 64, except a final chunk of up to 68 (buffer row = 68).
__device__ __forceinline__ int nchunks(int kdim) {
    return (kdim <= 68) ? 1 : ((kdim + 59) >> 6);
}

// buffer layout per chunk: [ h: 32 rows x 68 | w: 96 rows x 68 ], double buffered
#define TRR    32
#define RT     4
#define SM_HW  (TRR * 68)
#define SM_BUF (TRR * 68 + 96 * 68)
#define SM_BYTES (2 * SM_BUF * 4)          // 69632
#define SM_DEC_BYTES (SM_BYTES + 64 * 4)   // + pred_s region

// ---------------------------------------------------------------------------
// Stage one K-chunk (width W floats, W % 4 == 0, W <= 68) of activations
// (32 rows) + weights (3 x nv valid rows) via cp.async. Rows for invalid
// units (j >= whid) are NOT staged: dead lanes compute garbage that is
// never stored (epilogue guards j < hid).
// ---------------------------------------------------------------------------
__device__ __forceinline__ void stage_chunk(
    float* buf,
    const float* __restrict__ act, long actStride,
    const float* __restrict__ W, int wstride, int whid,
    int jt0, int rb0, int kc, int width, int nv, int tid)
{
    float* hbuf = buf;
    float* wbuf = buf + SM_HW;
    if (width == 64 && nv == 32) {
        for (int idx = tid; idx < 2048; idx += 256) {
            if (idx < 512) {
                int r = idx >> 4, q = idx & 15;
                cpa16(hbuf + r * 68 + q * 4,
                      act + (long)(rb0 + r) * actStride + kc + q * 4);
            } else {
                int wv = idx - 512;
                int rr = wv >> 4, q = wv & 15;
                cpa16(wbuf + rr * 68 + q * 4,
                      W + ((long)(rr >> 5) * whid + jt0 + (rr & 31)) * wstride
                        + kc + q * 4);
            }
        }
    } else {
        int wq = width >> 2;           // float4s per row (<= 17)
        int nh = TRR * wq;
        int nw = 3 * nv * wq;
        for (int idx = tid; idx < nh + nw; idx += 256) {
            if (idx < nh) {
                int r = idx / wq, q = idx - r * wq;
                cpa16(hbuf + r * 68 + q * 4,
                      act + (long)(rb0 + r) * actStride + kc + q * 4);
            } else {
                int wv = idx - nh;
                int rr = wv / wq, q = wv - rr * wq;
                int g = rr / nv, jj = rr - g * nv;
                cpa16(wbuf + (g * 32 + jj) * 68 + q * 4,
                      W + ((long)g * whid + jt0 + jj) * wstride + kc + q * 4);
            }
        }
    }
}

// ---------------------------------------------------------------------------
// Compute one staged chunk: 4 rows x (r,z,n) per thread, packed f32x2.
// ---------------------------------------------------------------------------
__device__ __forceinline__ void compute_chunk(
    const float* hb, const float* wr, const float* wz, const float* wn,
    int klim, ull* aR, ull* aZ, ull* aN)
{
#define CK_BODY(k) { \
    ulonglong2 r2 = *(const ulonglong2*)(wr + (k)); \
    ulonglong2 z2 = *(const ulonglong2*)(wz + (k)); \
    ulonglong2 n2 = *(const ulonglong2*)(wn + (k)); \
    _Pragma("unroll") \
    for (int i = 0; i < RT; i++) { \
        ulonglong2 h2 = *(const ulonglong2*)(hb + i * 68 + (k)); \
        fma2(aR[i], h2.x, r2.x); fma2(aR[i], h2.y, r2.y); \
        fma2(aZ[i], h2.x, z2.x); fma2(aZ[i], h2.y, z2.y); \
        fma2(aN[i], h2.x, n2.x); fma2(aN[i], h2.y, n2.y); \
    } }
    if (klim == 64) {
        #pragma unroll 8
        for (int k = 0; k < 64; k += 4) CK_BODY(k)
    } else {
        for (int k = 0; k < klim; k += 4) CK_BODY(k)
    }
#undef CK_BODY
}

// ---------------------------------------------------------------------------
// Fused hidden+input accumulation: continuous double-buffered pipeline.
// ---------------------------------------------------------------------------
struct ChunkP { const float* act; long stride; const float* W; int wstr;
                int base; int width; int isH; };

__device__ __forceinline__ void chunk_params(
    int c, int nH, int hid,
    const float* actH, const float* WH,
    const float* actA, long strideA, int kA,
    const float* WA, int wstrideA, ChunkP& p)
{
    if (c < nH) {
        p.act = actH; p.stride = hid; p.W = WH; p.wstr = hid;
        p.base = c * 64;
        p.width = (c == nH - 1) ? (hid - p.base) : 64;
        p.isH = 1;
    } else {
        int cc = c - nH;
        int nA = nchunks(kA);
        p.act = actA; p.stride = strideA; p.W = WA; p.wstr = wstrideA;
        p.base = cc * 64;
        p.width = (cc == nA - 1) ? (kA - p.base) : 64;
        p.isH = 0;
    }
}

__device__ __forceinline__ void accum_dual(
    float* sm, int whid, int nv,
    const float* __restrict__ actH, int hid, const float* __restrict__ WH,
    const float* __restrict__ actA, long strideA, int kA,
    const float* __restrict__ WA, int wstrideA,
    int jt0, int rb0, int tid, int lane, int warp,
    ull* aR, ull* aZ, ull* aNh, ull* aNi)
{
    int nH = nchunks(hid);
    int nA = (kA > 0) ? nchunks(kA) : 0;
    int nch = nH + nA;

    ChunkP p;
    chunk_params(0, nH, hid, actH, WH, actA, strideA, kA, WA, wstrideA, p);
    stage_chunk(sm, p.act, p.stride, p.W, p.wstr, whid, jt0, rb0,
                p.base, p.width, nv, tid);
    cpa_commit();
    for (int c = 0; c < nch; c++) {
        float* cur = sm + (c & 1) * SM_BUF;
        chunk_params(c, nH, hid, actH, WH, actA, strideA, kA, WA, wstrideA, p);
        if (c + 1 < nch) {
            ChunkP pn;
            chunk_params(c + 1, nH, hid, actH, WH, actA, strideA, kA, WA, wstrideA, pn);
            stage_chunk(sm + ((c + 1) & 1) * SM_BUF, pn.act, pn.stride,
                        pn.W, pn.wstr, whid, jt0, rb0, pn.base, pn.width, nv, tid);
            cpa_commit();
            cpa_wait<1>();
        } else {
            cpa_wait<0>();
        }
        __syncthreads();
        ull* aN = p.isH ? aNh : aNi;
        compute_chunk(cur + warp * RT * 68,
                      cur + SM_HW + lane * 68,
                      cur + SM_HW + (32 + lane) * 68,
                      cur + SM_HW + (64 + lane) * 68,
                      p.width, aR, aZ, aN);
        __syncthreads();
    }
}

// Direct gmem/smem pass for small input dims (<=32): no staging, scalar fp32.
__device__ __forceinline__ void accum_direct(
    const float* __restrict__ act, long actStride, int kdim,
    const float* __restrict__ W, int wstride, int whid,
    int j, int row0, float* gR, float* gZ, float* gN)
{
    if (j >= whid) return;
    for (int k = 0; k < kdim; k++) {
        float wr = W[(long)j * wstride + k];
        float wz = W[((long)whid + j) * wstride + k];
        float wn = W[((long)2 * whid + j) * wstride + k];
        #pragma unroll
        for (int i = 0; i < RT; i++) {
            float xv = act[(long)(row0 + i) * actStride + k];
            gR[i] = fmaf(xv, wr, gR[i]);
            gZ[i] = fmaf(xv, wz, gZ[i]);
            gN[i] = fmaf(xv, wn, gN[i]);
        }
    }
}

// ---------------------------------------------------------------------------
// GRU tile body: 32 rows x 32 units, 256 threads.
// ---------------------------------------------------------------------------
__device__ __forceinline__ void gru_tile(
    float* sm,
    const float* __restrict__ Hprev, float* __restrict__ Hnext,
    const float* __restrict__ XA, int dimA, long strideA,
    const float* __restrict__ XB, int dimB, long strideB,
    const float* __restrict__ Wih, const float* __restrict__ Whh,
    const float* __restrict__ bih, const float* __restrict__ bhh,
    const int* __restrict__ mask, int maskStride,
    float* __restrict__ mOut, int hid,
    int rb0, int jt0)
{
    int tid = threadIdx.x, lane = tid & 31, warp = tid >> 5;
    int j = jt0 + lane;
    int row0 = rb0 + warp * RT;
    int in_dim = dimA + dimB;
    int nv = hid - jt0; if (nv > 32) nv = 32;

    ull aR[RT], aZ[RT], aNh[RT], aNi[RT];
    float gR[RT], gZ[RT], gN[RT];
    #pragma unroll
    for (int i = 0; i < RT; i++) {
        aR[i] = 0; aZ[i] = 0; aNh[i] = 0; aNi[i] = 0;
        gR[i] = 0.f; gZ[i] = 0.f; gN[i] = 0.f;
    }

    if (dimA > 32) {
        accum_dual(sm, hid, nv, Hprev, hid, Whh, XA, strideA, dimA, Wih, in_dim,
                   jt0, rb0, tid, lane, warp, aR, aZ, aNh, aNi);
    } else {
        accum_dual(sm, hid, nv, Hprev, hid, Whh,
                   (const float*)nullptr, 0L, 0, (const float*)nullptr, 0,
                   jt0, rb0, tid, lane, warp, aR, aZ, aNh, aNi);
        if (dimA > 0)
            accum_direct(XA, strideA, dimA, Wih, in_dim, hid,
                         j, row0, gR, gZ, gN);
    }
    if (dimB > 0)
        accum_direct(XB, strideB, dimB, Wih + dimA, in_dim, hid,
                     j, row0, gR, gZ, gN);

    if (j >= hid) return;

    float bR  = bih[j] + bhh[j];
    float bZ  = bih[hid + j] + bhh[hid + j];
    float bNi = bih[2 * hid + j];
    float bNh = bhh[2 * hid + j];
    #pragma unroll
    for (int i = 0; i < RT; i++) {
        int row = row0 + i;
        float hold = Hprev[(long)row * hid + j];
        float r = sigm(hsum2(aR[i]) + gR[i] + bR);
        float z = sigm(hsum2(aZ[i]) + gZ[i] + bZ);
        float n = tanhf(hsum2(aNi[i]) + gN[i] + bNi + r * (hsum2(aNh[i]) + bNh));
        float hn = (1.f - z) * n + z * hold;
        int mv = mask ? mask[(long)row * maskStride] : 1;
        float hf = mv ? hn : hold;
        Hnext[(long)row * hid + j] = hf;
        if (mOut && j < HH)
            mOut[(long)row * HH + j] = mv ? hf : 0.f;
    }
}

// ---------------------------------------------------------------------------
// Generic GRU step kernel (enc l0(0), decoder l1).
// ---------------------------------------------------------------------------
__global__ __launch_bounds__(256, 2) void k_gru(
    const float* __restrict__ Hprev, float* __restrict__ Hnext,
    const float* __restrict__ XA, int dimA, long strideA,
    const float* __restrict__ XB, int dimB, long strideB,
    const float* __restrict__ Wih, const float* __restrict__ Whh,
    const float* __restrict__ bih, const float* __restrict__ bhh,
    const int* __restrict__ mask, int maskStride,
    float* __restrict__ mOut, int hid)
{
    extern __shared__ __align__(16) float sm[];
    gru_tile(sm, Hprev, Hnext, XA, dimA, strideA, XB, dimB, strideB,
             Wih, Whh, bih, bhh, mask, maskStride, mOut, hid,
             blockIdx.x * TRR, blockIdx.y * 32);
}

// ---------------------------------------------------------------------------
// Fused encoder step: one launch computes l0(t+1) AND l1(t) (independent).
// grid = (32, 16): y<8 -> l0(t+1) unit tiles, y>=8 -> l1(t) unit tiles.
// ---------------------------------------------------------------------------
__global__ __launch_bounds__(256, 2) void k_enc_step(
    const float* __restrict__ Xin, float* __restrict__ Xout,
    const float* __restrict__ Yin, float* __restrict__ Yout,
    const float* __restrict__ x, const float* __restrict__ feat,
    const int* __restrict__ mask, int t, int do_l0,
    const float* __restrict__ eWih0, const float* __restrict__ eWhh0,
    const float* __restrict__ ebih0, const float* __restrict__ ebhh0,
    const float* __restrict__ eWih1, const float* __restrict__ eWhh1,
    const float* __restrict__ ebih1, const float* __restrict__ ebhh1,
    float* __restrict__ encout)
{
    extern __shared__ __align__(16) float sm[];
    int rb0 = blockIdx.x * TRR;
    if (blockIdx.y < 8) {
        if (!do_l0) return;
        int tn = t + 1;
        gru_tile(sm, Xin, Xout,
                 x + (long)tn * 2, 2, (long)TENC * 2,
                 feat + (long)tn * FF, FF, (long)TT * FF,
                 eWih0, eWhh0, ebih0, ebhh0,
                 mask + tn, TENC, (float*)nullptr, HE,
                 rb0, blockIdx.y * 32);
    } else {
        gru_tile(sm, Yin, Yout,
                 Xin, HE, (long)HE,
                 (const float*)nullptr, 0, 0L,
                 eWih1, eWhh1, ebih1, ebhh1,
                 mask + t, TENC,
                 encout + (long)t * BB * HH, HE,
                 rb0, (blockIdx.y - 8) * 32);
    }
}

// ---------------------------------------------------------------------------
// Fused decoder l0 step: mlp(d1(t-1)) inline (when do_mlp) + GRU layer 0.
// grid = (256, 5), block 256, dyn smem SM_DEC_BYTES.
// ---------------------------------------------------------------------------
__global__ __launch_bounds__(256, 2) void k_dec0(
    const float* __restrict__ Hprev, float* __restrict__ Hnext,
    const float* __restrict__ D1prev, const float* __restrict__ Xfallback,
    const float* __restrict__ W1, const float* __restrict__ b1,
    const float* __restrict__ W2, const float* __restrict__ b2,
    float* __restrict__ outb, int tstep, int do_mlp,
    const float* __restrict__ dWih0, const float* __restrict__ dWhh0,
    const float* __restrict__ dbih0, const float* __restrict__ dbhh0)
{
    extern __shared__ __align__(16) float sm[];
    float* pred_s = sm + 2 * SM_BUF;
    int tid = threadIdx.x;
    int rb0 = blockIdx.x * TRR;
    const float* XA;
    long strideA;
    if (do_mlp) {
        // phase A: h1 = relu(W1 @ d1row + b1); 32 rows x 64 outs
        int r = tid >> 3, o0 = (tid & 7) * 8;
        const float4* dp4 = (const float4*)(D1prev + (long)(rb0 + r) * HD);
        const float4* w14 = (const float4*)W1;
        float acc[8];
        #pragma unroll
        for (int i = 0; i < 8; i++) acc[i] = b1[o0 + i];
        for (int k4 = 0; k4 < 32; k4++) {
            float4 d = dp4[k4];
            #pragma unroll
            for (int i = 0; i < 8; i++) {
                float4 w = w14[(o0 + i) * 32 + k4];
                acc[i] = fmaf(d.x, w.x, fmaf(d.y, w.y,
                         fmaf(d.z, w.z, fmaf(d.w, w.w, acc[i]))));
            }
        }
        #pragma unroll
        for (int i = 0; i < 8; i++)
            sm[r * 68 + o0 + i] = fmaxf(acc[i], 0.f);
        __syncthreads();
        // phase B: pred = softplus(W2 @ h1 + b2); 32 rows x 2
        if (tid < 64) {
            int r2 = tid >> 1, c = tid & 1;
            const float* hp = sm + r2 * 68;
            const float* wp = W2 + c * 64;
            float a = b2[c];
            #pragma unroll 8
            for (int k = 0; k < 64; k++) a = fmaf(hp[k], wp[k], a);
            float pred = softp(a);
            pred_s[r2 * 2 + c] = pred;
            if (blockIdx.y == 0)
                outb[DEC_BASE + (long)(rb0 + r2) * 128 + tstep * 2 + c] = pred;
        }
        __syncthreads();
        XA = pred_s - (long)rb0 * 2;   // accum_direct indexes act[row*2 + k]
        strideA = 2L;
    } else {
        XA = Xfallback;
        strideA = 2L;
    }
    gru_tile(sm, Hprev, Hnext, XA, 2, strideA,
             (const float*)nullptr, 0, 0L,
             dWih0, dWhh0, dbih0, dbhh0,
             (const int*)nullptr, 0, (float*)nullptr, HD,
             rb0, blockIdx.y * 32);
}

// ---------------------------------------------------------------------------
// MLP: softplus(relu(h @ W1^T + b1) @ W2^T + b2), 16 rows per block.
// ---------------------------------------------------------------------------
__global__ __launch_bounds__(256) void k_mlp(
    const float* __restrict__ Hin, int hstride,
    const float* __restrict__ W1, const float* __restrict__ b1,
    const float* __restrict__ W2, const float* __restrict__ b2,
    float* __restrict__ outb, float* __restrict__ dout,
    float* __restrict__ glast, int mode, int tstep)
{
    __shared__ __align__(16) float w1s[64 * 132];
    __shared__ __align__(16) float hs[16 * 132];
    __shared__ float h1s[16 * 68];
    __shared__ float w2s[128];
    __shared__ float b1s[64];
    __shared__ float b2s[2];

    int tid = threadIdx.x;
    int row0 = blockIdx.x * 16;

    for (int idx = tid; idx < 64 * 128; idx += 256) {
        int o = idx >> 7, k = idx & 127;
        w1s[o * 132 + k] = W1[idx];
    }
    for (int idx = tid; idx < 16 * 128; idx += 256) {
        int rr = idx >> 7, k = idx & 127;
        hs[rr * 132 + k] = Hin[(long)(row0 + rr) * hstride + k];
    }
    if (tid < 128) w2s[tid] = W2[tid];
    if (tid < 64)  b1s[tid] = b1[tid];
    if (tid < 2)   b2s[tid] = b2[tid];
    __syncthreads();

    #pragma unroll
    for (int p = 0; p < 4; p++) {
        int idx = p * 256 + tid;
        int o = idx & 63, rr = idx >> 6;
        const float* wp = w1s + o * 132;
        const float* hp = hs + rr * 132;
        float acc = b1s[o];
        #pragma unroll 8
        for (int k = 0; k < 128; k += 4) {
            float4 w4 = *(const float4*)(wp + k);
            float4 h4 = *(const float4*)(hp + k);
            acc = fmaf(w4.x, h4.x, acc);
            acc = fmaf(w4.y, h4.y, acc);
            acc = fmaf(w4.z, h4.z, acc);
            acc = fmaf(w4.w, h4.w, acc);
        }
        h1s[rr * 68 + o] = fmaxf(acc, 0.f);
    }
    __syncthreads();

    if (tid < 32) {
        int rr = tid >> 1, c = tid & 1;
        const float* hp = h1s + rr * 68;
        const float* wp = w2s + c * 64;
        float acc = b2s[c];
        #pragma unroll 8
        for (int k = 0; k < 64; k++) acc = fmaf(hp[k], wp[k], acc);
        float pred = softp(acc);
        int row = row0 + rr;
        if (mode == 0) {
            int t = row >> 10, b = row & 1023;
            if (t < 127) {
                long off = (long)b * 254 + t * 2 + c;
                #pragma unroll
                for (int s = 0; s < SS; s++)
                    outb[(long)s * ENC_SSTRIDE + off] = pred;
            } else {
                glast[b * 2 + c] = pred;
                #pragma unroll
                for (int s = 0; s < SS; s++)
                    outb[DEC_BASE + (long)((s << 10) | b) * 128 + c] = pred;
            }
        } else {
            dout[row * 2 + c] = pred;
            outb[DEC_BASE + (long)row * 128 + tstep * 2 + c] = pred;
        }
    }
}

// ---------------------------------------------------------------------------
// Reparameterization + decoder initial hidden states
// ---------------------------------------------------------------------------
__global__ void k_z(
    const float* __restrict__ hf0, const float* __restrict__ hf1,
    const float* __restrict__ eps, const float* __restrict__ feat,
    float* __restrict__ dh0, float* __restrict__ dh1)
{
    int idx = blockIdx.x * blockDim.x + threadIdx.x;
    if (idx >= SB * HD) return;
    int row = idx / HD, j = idx - row * HD;
    int s = row >> 10, b = row & 1023;
    float v0, v1;
    if (j < HH) {
        float m0 = hf0[b * HE + j],  lv0 = hf0[b * HE + HH + j];
        float m1 = hf1[b * HE + j],  lv1 = hf1[b * HE + HH + j];
        float e0 = eps[(((long)(s * 2 + 0) * BB + b) * HH) + j];
        float e1 = eps[(((long)(s * 2 + 1) * BB + b) * HH) + j];
        v0 = e0 * expf(0.5f * lv0) + m0;
        v1 = e1 * expf(0.5f * lv1) + m1;
    } else {
        float fc = feat[((long)b * TT + TENC) * FF + (j - HH)];
        v0 = fc; v1 = fc;
    }
    dh0[idx] = v0;
    dh1[idx] = v1;
}

__global__ void k_bcast_last(const float* __restrict__ last, float* __restrict__ dout)
{
    int i = blockIdx.x * blockDim.x + threadIdx.x;
    if (i < SB * 2) {
        int row = i >> 1, c = i & 1;
        dout[i] = last[((row & 1023) << 1) | c];
    }
}

__global__ void k_zero2(float* a, float* b, int n)
{
    int i = blockIdx.x * blockDim.x + threadIdx.x;
    if (i < n) { a[i] = 0.f; b[i] = 0.f; }
}

// ---------------------------------------------------------------------------
// Host orchestration (single stream, graph-capturable)
// ---------------------------------------------------------------------------
extern "C" void kernel_launch(void* const* d_in, const int* in_sizes, int n_in,
                              void* d_out, int out_size)
{
    const float* x    = (const float*)d_in[0];
    const float* feat = (const float*)d_in[1];
    const int*   mask = (const int*)d_in[2];
    const float* eps  = (const float*)d_in[3];

    int base = (n_in > 7 && in_sizes[4] == 1) ? 7 : 4;
    const float* eWih0 = (const float*)d_in[base + 0];
    const float* eWhh0 = (const float*)d_in[base + 1];
    const float* ebih0 = (const float*)d_in[base + 2];
    const float* ebhh0 = (const float*)d_in[base + 3];
    const float* eWih1 = (const float*)d_in[base + 4];
    const float* eWhh1 = (const float*)d_in[base + 5];
    const float* ebih1 = (const float*)d_in[base + 6];
    const float* ebhh1 = (const float*)d_in[base + 7];
    const float* dWih0 = (const float*)d_in[base + 8];
    const float* dWhh0 = (const float*)d_in[base + 9];
    const float* dbih0 = (const float*)d_in[base + 10];
    const float* dbhh0 = (const float*)d_in[base + 11];
    const float* dWih1 = (const float*)d_in[base + 12];
    const float* dWhh1 = (const float*)d_in[base + 13];
    const float* dbih1 = (const float*)d_in[base + 14];
    const float* dbhh1 = (const float*)d_in[base + 15];
    const float* W1    = (const float*)d_in[base + 16];
    const float* b1    = (const float*)d_in[base + 17];
    const float* W2    = (const float*)d_in[base + 18];
    const float* b2    = (const float*)d_in[base + 19];

    float* outb = (float*)d_out;

    float *p_h0, *p_h1, *p_enc, *p_last, *p_dh0, *p_dh1, *p_dout;
    cudaGetSymbolAddress((void**)&p_h0,   g_h0);
    cudaGetSymbolAddress((void**)&p_h1,   g_h1);
    cudaGetSymbolAddress((void**)&p_enc,  g_enc);
    cudaGetSymbolAddress((void**)&p_last, g_last);
    cudaGetSymbolAddress((void**)&p_dh0,  g_dh0);
    cudaGetSymbolAddress((void**)&p_dh1,  g_dh1);
    cudaGetSymbolAddress((void**)&p_dout, g_dout);

    cudaFuncSetAttribute(k_gru, cudaFuncAttributeMaxDynamicSharedMemorySize, SM_BYTES);
    cudaFuncSetAttribute(k_enc_step, cudaFuncAttributeMaxDynamicSharedMemorySize, SM_BYTES);
    cudaFuncSetAttribute(k_dec0, cudaFuncAttributeMaxDynamicSharedMemorySize, SM_DEC_BYTES);

    const int HSZ = BB * HE;
    const int DSZ = SB * HD;
    float* X[2] = {p_h0, p_h0 + HSZ};
    float* Y[2] = {p_h1, p_h1 + HSZ};

    k_zero2<<<(HSZ + 255) / 256, 256>>>(p_h0, p_h1, HSZ);

    // ---------------- encoder: fused l0(t+1)+l1(t) chain ----------------
    dim3 eg0(BB / 32, 8);
    k_gru<<<eg0, 256, SM_BYTES>>>(X[0], X[1],
        x, 2, (long)TENC * 2, feat, FF, (long)TT * FF,
        eWih0, eWhh0, ebih0, ebhh0, mask, TENC, (float*)nullptr, HE);
    dim3 egf(BB / 32, 16);
    for (int t = 0; t < TENC; t++) {
        k_enc_step<<<egf, 256, SM_BYTES>>>(
            X[(t + 1) & 1], X[t & 1], Y[t & 1], Y[(t + 1) & 1],
            x, feat, mask, t, (t + 1 < TENC) ? 1 : 0,
            eWih0, eWhh0, ebih0, ebhh0,
            eWih1, eWhh1, ebih1, ebhh1, p_enc);
    }

    // ---------------- reparameterize + encoder MLP ----------------
    k_z<<<(SB * HD + 255) / 256, 256>>>(X[0], Y[0], eps, feat, p_dh0, p_dh1);
    k_mlp<<<(TENC * BB) / 16, 256>>>(p_enc, HH, W1, b1, W2, b2,
                                     outb, (float*)nullptr, p_last, 0, 0);
    k_bcast_last<<<(SB * 2 + 255) / 256, 256>>>(p_last, p_dout);

    // ---------------- decoder scan (mlp fused into l0) ----------------
    float* d0c = p_dh0;       float* d0n = p_dh0 + DSZ;
    float* d1c = p_dh1;       float* d1n = p_dh1 + DSZ;
    dim3 dgrid(SB / 32, (HD + 31) / 32);   // (256, 5)
    for (int t = 1; t < TDEC; t++) {
        k_dec0<<<dgrid, 256, SM_DEC_BYTES>>>(d0c, d0n, d1c, p_dout,
                              W1, b1, W2, b2, outb, t - 1, (t >= 2) ? 1 : 0,
                              dWih0, dWhh0, dbih0, dbhh0);
        k_gru<<<dgrid, 256, SM_BYTES>>>(d1c, d1n,
                              d0n, HD, (long)HD,
                              (const float*)nullptr, 0, 0L,
                              dWih1, dWhh1, dbih1, dbhh1,
                              (const int*)nullptr, 0, (float*)nullptr, HD);
        float* tmp;
        tmp = d0c; d0c = d0n; d0n = tmp;
        tmp = d1c; d1c = d1n; d1n = tmp;
    }
    // final output step (t = TDEC-1 = 63)
    k_mlp<<<SB / 16, 256>>>(d1c, HD, W1, b1, W2, b2,
                            outb, p_dout, (float*)nullptr, 1, TDEC - 1);
}

// round 14
// speedup vs baseline: 1.9561x; 1.9561x over previous
#include <cuda_runtime.h>
#include <cuda_bf16.h>
#include <math.h>

// ---------------------------------------------------------------------------
// Problem constants
// ---------------------------------------------------------------------------
#define BB    1024
#define TENC  128
#define TDEC  64
#define HH    128
#define FF    16
#define SS    8
#define HE    256
#define HD    132
#define SB    (SS*BB)
#define TT    (TENC+TDEC)
#define DEC_BASE 2080768    // 8*1024*127*2
#define ENC_SSTRIDE 260096  // 1024*127*2

typedef unsigned long long ull;

// ---------------------------------------------------------------------------
// Device scratch
// ---------------------------------------------------------------------------
__device__ __align__(128) float g_h0[2 * BB * HE];
__device__ __align__(128) float g_h1[2 * BB * HE];
__device__ __align__(128) float g_enc[TENC * BB * HH];
__device__ __align__(128) float g_last[BB * 2];
__device__ __align__(128) float g_dh0[2 * SB * HD];
__device__ __align__(128) float g_dh1[2 * SB * HD];
__device__ __align__(128) float g_dout[SB * 2];

// ---------------------------------------------------------------------------
// Helpers
// ---------------------------------------------------------------------------
__device__ __forceinline__ float sigm(float x)  { return 1.f / (1.f + __expf(-x)); }
__device__ __forceinline__ float tanhff(float x){ return 2.f / (1.f + __expf(-2.f * x)) - 1.f; }
__device__ __forceinline__ float softp(float x) {
    return fmaxf(x, 0.f) + log1pf(expf(-fabsf(x)));
}
__device__ __forceinline__ void fma2(ull &d, ull a, ull b) {
    asm("fma.rn.f32x2 %0, %1, %2, %0;" : "+l"(d) : "l"(a), "l"(b));
}
__device__ __forceinline__ float hsum2(ull v) {
    float lo = __uint_as_float((unsigned)(v & 0xffffffffull));
    float hi = __uint_as_float((unsigned)(v >> 32));
    return lo + hi;
}
__device__ __forceinline__ void cpa16(float* dst, const float* src) {
    unsigned sa = (unsigned)__cvta_generic_to_shared(dst);
    asm volatile("cp.async.cg.shared.global [%0], [%1], 16;\n" :: "r"(sa), "l"(src));
}
__device__ __forceinline__ void cpa_commit() { asm volatile("cp.async.commit_group;\n"); }
template<int N> __device__ __forceinline__ void cpa_wait() {
    asm volatile("cp.async.wait_group %0;\n" :: "n"(N));
}

// Chunking: chunks of 64, except a final chunk of up to 68 (buffer row = 68).
__device__ __forceinline__ int nchunks(int kdim) {
    return (kdim <= 68) ? 1 : ((kdim + 59) >> 6);
}

// buffer layout per chunk: [ h: 32 rows x 68 | w: 96 rows x 68 ], double buffered
#define TRR    32
#define RT     4
#define SM_HW  (TRR * 68)
#define SM_BUF (TRR * 68 + 96 * 68)
#define SM_BYTES (2 * SM_BUF * 4)          // 69632

// ---------------------------------------------------------------------------
// Stage one K-chunk (width W floats, W % 4 == 0, W <= 68) of activations
// (32 rows) + weights (3 x nv valid rows) via cp.async. Rows for invalid
// units (j >= whid) are NOT staged: dead lanes compute garbage that is
// never stored (epilogue guards j < hid).
// ---------------------------------------------------------------------------
__device__ __forceinline__ void stage_chunk(
    float* buf,
    const float* __restrict__ act, long actStride,
    const float* __restrict__ W, int wstride, int whid,
    int jt0, int rb0, int kc, int width, int nv, int tid)
{
    float* hbuf = buf;
    float* wbuf = buf + SM_HW;
    if (width == 64 && nv == 32) {
        for (int idx = tid; idx < 2048; idx += 256) {
            if (idx < 512) {
                int r = idx >> 4, q = idx & 15;
                cpa16(hbuf + r * 68 + q * 4,
                      act + (long)(rb0 + r) * actStride + kc + q * 4);
            } else {
                int wv = idx - 512;
                int rr = wv >> 4, q = wv & 15;
                cpa16(wbuf + rr * 68 + q * 4,
                      W + ((long)(rr >> 5) * whid + jt0 + (rr & 31)) * wstride
                        + kc + q * 4);
            }
        }
    } else {
        int wq = width >> 2;           // float4s per row (<= 17)
        int nh = TRR * wq;
        int nw = 3 * nv * wq;
        for (int idx = tid; idx < nh + nw; idx += 256) {
            if (idx < nh) {
                int r = idx / wq, q = idx - r * wq;
                cpa16(hbuf + r * 68 + q * 4,
                      act + (long)(rb0 + r) * actStride + kc + q * 4);
            } else {
                int wv = idx - nh;
                int rr = wv / wq, q = wv - rr * wq;
                int g = rr / nv, jj = rr - g * nv;
                cpa16(wbuf + (g * 32 + jj) * 68 + q * 4,
                      W + ((long)g * whid + jt0 + jj) * wstride + kc + q * 4);
            }
        }
    }
}

// ---------------------------------------------------------------------------
// Compute one staged chunk: 4 rows x (r,z,n) per thread, packed f32x2.
// ---------------------------------------------------------------------------
__device__ __forceinline__ void compute_chunk(
    const float* hb, const float* wr, const float* wz, const float* wn,
    int klim, ull* aR, ull* aZ, ull* aN)
{
#define CK_BODY(k) { \
    ulonglong2 r2 = *(const ulonglong2*)(wr + (k)); \
    ulonglong2 z2 = *(const ulonglong2*)(wz + (k)); \
    ulonglong2 n2 = *(const ulonglong2*)(wn + (k)); \
    _Pragma("unroll") \
    for (int i = 0; i < RT; i++) { \
        ulonglong2 h2 = *(const ulonglong2*)(hb + i * 68 + (k)); \
        fma2(aR[i], h2.x, r2.x); fma2(aR[i], h2.y, r2.y); \
        fma2(aZ[i], h2.x, z2.x); fma2(aZ[i], h2.y, z2.y); \
        fma2(aN[i], h2.x, n2.x); fma2(aN[i], h2.y, n2.y); \
    } }
    if (klim == 64) {
        #pragma unroll 8
        for (int k = 0; k < 64; k += 4) CK_BODY(k)
    } else {
        for (int k = 0; k < klim; k += 4) CK_BODY(k)
    }
#undef CK_BODY
}

// ---------------------------------------------------------------------------
// Fused hidden+input accumulation: continuous double-buffered pipeline.
// ---------------------------------------------------------------------------
struct ChunkP { const float* act; long stride; const float* W; int wstr;
                int base; int width; int isH; };

__device__ __forceinline__ void chunk_params(
    int c, int nH, int hid,
    const float* actH, const float* WH,
    const float* actA, long strideA, int kA,
    const float* WA, int wstrideA, ChunkP& p)
{
    if (c < nH) {
        p.act = actH; p.stride = hid; p.W = WH; p.wstr = hid;
        p.base = c * 64;
        p.width = (c == nH - 1) ? (hid - p.base) : 64;
        p.isH = 1;
    } else {
        int cc = c - nH;
        int nA = nchunks(kA);
        p.act = actA; p.stride = strideA; p.W = WA; p.wstr = wstrideA;
        p.base = cc * 64;
        p.width = (cc == nA - 1) ? (kA - p.base) : 64;
        p.isH = 0;
    }
}

__device__ __forceinline__ void accum_dual(
    float* sm, int whid, int nv,
    const float* __restrict__ actH, int hid, const float* __restrict__ WH,
    const float* __restrict__ actA, long strideA, int kA,
    const float* __restrict__ WA, int wstrideA,
    int jt0, int rb0, int tid, int lane, int warp,
    ull* aR, ull* aZ, ull* aNh, ull* aNi)
{
    int nH = nchunks(hid);
    int nA = (kA > 0) ? nchunks(kA) : 0;
    int nch = nH + nA;

    ChunkP p;
    chunk_params(0, nH, hid, actH, WH, actA, strideA, kA, WA, wstrideA, p);
    stage_chunk(sm, p.act, p.stride, p.W, p.wstr, whid, jt0, rb0,
                p.base, p.width, nv, tid);
    cpa_commit();
    for (int c = 0; c < nch; c++) {
        float* cur = sm + (c & 1) * SM_BUF;
        chunk_params(c, nH, hid, actH, WH, actA, strideA, kA, WA, wstrideA, p);
        if (c + 1 < nch) {
            ChunkP pn;
            chunk_params(c + 1, nH, hid, actH, WH, actA, strideA, kA, WA, wstrideA, pn);
            stage_chunk(sm + ((c + 1) & 1) * SM_BUF, pn.act, pn.stride,
                        pn.W, pn.wstr, whid, jt0, rb0, pn.base, pn.width, nv, tid);
            cpa_commit();
            cpa_wait<1>();
        } else {
            cpa_wait<0>();
        }
        __syncthreads();
        ull* aN = p.isH ? aNh : aNi;
        compute_chunk(cur + warp * RT * 68,
                      cur + SM_HW + lane * 68,
                      cur + SM_HW + (32 + lane) * 68,
                      cur + SM_HW + (64 + lane) * 68,
                      p.width, aR, aZ, aN);
        __syncthreads();
    }
}

// Direct gmem pass for small input dims (<=32): no staging, scalar fp32.
__device__ __forceinline__ void accum_direct(
    const float* __restrict__ act, long actStride, int kdim,
    const float* __restrict__ W, int wstride, int whid,
    int j, int row0, float* gR, float* gZ, float* gN)
{
    if (j >= whid) return;
    for (int k = 0; k < kdim; k++) {
        float wr = W[(long)j * wstride + k];
        float wz = W[((long)whid + j) * wstride + k];
        float wn = W[((long)2 * whid + j) * wstride + k];
        #pragma unroll
        for (int i = 0; i < RT; i++) {
            float xv = act[(long)(row0 + i) * actStride + k];
            gR[i] = fmaf(xv, wr, gR[i]);
            gZ[i] = fmaf(xv, wz, gZ[i]);
            gN[i] = fmaf(xv, wn, gN[i]);
        }
    }
}

// ---------------------------------------------------------------------------
// GRU tile body: 32 rows x 32 units, 256 threads.
// ---------------------------------------------------------------------------
__device__ __forceinline__ void gru_tile(
    float* sm,
    const float* __restrict__ Hprev, float* __restrict__ Hnext,
    const float* __restrict__ XA, int dimA, long strideA,
    const float* __restrict__ XB, int dimB, long strideB,
    const float* __restrict__ Wih, const float* __restrict__ Whh,
    const float* __restrict__ bih, const float* __restrict__ bhh,
    const int* __restrict__ mask, int maskStride,
    float* __restrict__ mOut, int hid,
    int rb0, int jt0)
{
    int tid = threadIdx.x, lane = tid & 31, warp = tid >> 5;
    int j = jt0 + lane;
    int row0 = rb0 + warp * RT;
    int in_dim = dimA + dimB;
    int nv = hid - jt0; if (nv > 32) nv = 32;

    // prefetch epilogue operands (latency hidden under GEMM)
    float hold[RT];
    int mv[RT];
    #pragma unroll
    for (int i = 0; i < RT; i++) {
        hold[i] = (j < hid) ? Hprev[(long)(row0 + i) * hid + j] : 0.f;
        mv[i] = mask ? mask[(long)(row0 + i) * maskStride] : 1;
    }

    ull aR[RT], aZ[RT], aNh[RT], aNi[RT];
    float gR[RT], gZ[RT], gN[RT];
    #pragma unroll
    for (int i = 0; i < RT; i++) {
        aR[i] = 0; aZ[i] = 0; aNh[i] = 0; aNi[i] = 0;
        gR[i] = 0.f; gZ[i] = 0.f; gN[i] = 0.f;
    }

    if (dimA > 32) {
        accum_dual(sm, hid, nv, Hprev, hid, Whh, XA, strideA, dimA, Wih, in_dim,
                   jt0, rb0, tid, lane, warp, aR, aZ, aNh, aNi);
    } else {
        accum_dual(sm, hid, nv, Hprev, hid, Whh,
                   (const float*)nullptr, 0L, 0, (const float*)nullptr, 0,
                   jt0, rb0, tid, lane, warp, aR, aZ, aNh, aNi);
        if (dimA > 0)
            accum_direct(XA, strideA, dimA, Wih, in_dim, hid,
                         j, row0, gR, gZ, gN);
    }
    if (dimB > 0)
        accum_direct(XB, strideB, dimB, Wih + dimA, in_dim, hid,
                     j, row0, gR, gZ, gN);

    if (j >= hid) return;

    float bR  = bih[j] + bhh[j];
    float bZ  = bih[hid + j] + bhh[hid + j];
    float bNi = bih[2 * hid + j];
    float bNh = bhh[2 * hid + j];
    #pragma unroll
    for (int i = 0; i < RT; i++) {
        int row = row0 + i;
        float r = sigm(hsum2(aR[i]) + gR[i] + bR);
        float z = sigm(hsum2(aZ[i]) + gZ[i] + bZ);
        float n = tanhff(hsum2(aNi[i]) + gN[i] + bNi + r * (hsum2(aNh[i]) + bNh));
        float hn = (1.f - z) * n + z * hold[i];
        float hf = mv[i] ? hn : hold[i];
        Hnext[(long)row * hid + j] = hf;
        if (mOut && j < HH)
            mOut[(long)row * HH + j] = mv[i] ? hf : 0.f;
    }
}

// ---------------------------------------------------------------------------
// Generic GRU step kernel (enc l0(0), decoder layers). 2 CTAs/SM.
// ---------------------------------------------------------------------------
__global__ __launch_bounds__(256, 2) void k_gru(
    const float* __restrict__ Hprev, float* __restrict__ Hnext,
    const float* __restrict__ XA, int dimA, long strideA,
    const float* __restrict__ XB, int dimB, long strideB,
    const float* __restrict__ Wih, const float* __restrict__ Whh,
    const float* __restrict__ bih, const float* __restrict__ bhh,
    const int* __restrict__ mask, int maskStride,
    float* __restrict__ mOut, int hid)
{
    extern __shared__ __align__(16) float sm[];
    gru_tile(sm, Hprev, Hnext, XA, dimA, strideA, XB, dimB, strideB,
             Wih, Whh, bih, bhh, mask, maskStride, mOut, hid,
             blockIdx.x * TRR, blockIdx.y * 32);
}

// ---------------------------------------------------------------------------
// Fused encoder step: one launch computes l0(t+1) AND l1(t) (independent).
// grid = (32, 16): y<8 -> l0(t+1), y>=8 -> l1(t). 3 CTAs/SM (occupancy bet).
// ---------------------------------------------------------------------------
__global__ __launch_bounds__(256, 3) void k_enc_step(
    const float* __restrict__ Xin, float* __restrict__ Xout,
    const float* __restrict__ Yin, float* __restrict__ Yout,
    const float* __restrict__ x, const float* __restrict__ feat,
    const int* __restrict__ mask, int t, int do_l0,
    const float* __restrict__ eWih0, const float* __restrict__ eWhh0,
    const float* __restrict__ ebih0, const float* __restrict__ ebhh0,
    const float* __restrict__ eWih1, const float* __restrict__ eWhh1,
    const float* __restrict__ ebih1, const float* __restrict__ ebhh1,
    float* __restrict__ encout)
{
    extern __shared__ __align__(16) float sm[];
    int rb0 = blockIdx.x * TRR;
    if (blockIdx.y < 8) {
        if (!do_l0) return;
        int tn = t + 1;
        gru_tile(sm, Xin, Xout,
                 x + (long)tn * 2, 2, (long)TENC * 2,
                 feat + (long)tn * FF, FF, (long)TT * FF,
                 eWih0, eWhh0, ebih0, ebhh0,
                 mask + tn, TENC, (float*)nullptr, HE,
                 rb0, blockIdx.y * 32);
    } else {
        gru_tile(sm, Yin, Yout,
                 Xin, HE, (long)HE,
                 (const float*)nullptr, 0, 0L,
                 eWih1, eWhh1, ebih1, ebhh1,
                 mask + t, TENC,
                 encout + (long)t * BB * HH, HE,
                 rb0, (blockIdx.y - 8) * 32);
    }
}

// ---------------------------------------------------------------------------
// MLP: softplus(relu(h @ W1^T + b1) @ W2^T + b2), 16 rows per block.
// ---------------------------------------------------------------------------
__global__ __launch_bounds__(256) void k_mlp(
    const float* __restrict__ Hin, int hstride,
    const float* __restrict__ W1, const float* __restrict__ b1,
    const float* __restrict__ W2, const float* __restrict__ b2,
    float* __restrict__ outb, float* __restrict__ dout,
    float* __restrict__ glast, int mode, int tstep)
{
    __shared__ __align__(16) float w1s[64 * 132];
    __shared__ __align__(16) float hs[16 * 132];
    __shared__ float h1s[16 * 68];
    __shared__ float w2s[128];
    __shared__ float b1s[64];
    __shared__ float b2s[2];

    int tid = threadIdx.x;
    int row0 = blockIdx.x * 16;

    for (int idx = tid; idx < 64 * 128; idx += 256) {
        int o = idx >> 7, k = idx & 127;
        w1s[o * 132 + k] = W1[idx];
    }
    for (int idx = tid; idx < 16 * 128; idx += 256) {
        int rr = idx >> 7, k = idx & 127;
        hs[rr * 132 + k] = Hin[(long)(row0 + rr) * hstride + k];
    }
    if (tid < 128) w2s[tid] = W2[tid];
    if (tid < 64)  b1s[tid] = b1[tid];
    if (tid < 2)   b2s[tid] = b2[tid];
    __syncthreads();

    #pragma unroll
    for (int p = 0; p < 4; p++) {
        int idx = p * 256 + tid;
        int o = idx & 63, rr = idx >> 6;
        const float* wp = w1s + o * 132;
        const float* hp = hs + rr * 132;
        float acc = b1s[o];
        #pragma unroll 8
        for (int k = 0; k < 128; k += 4) {
            float4 w4 = *(const float4*)(wp + k);
            float4 h4 = *(const float4*)(hp + k);
            acc = fmaf(w4.x, h4.x, acc);
            acc = fmaf(w4.y, h4.y, acc);
            acc = fmaf(w4.z, h4.z, acc);
            acc = fmaf(w4.w, h4.w, acc);
        }
        h1s[rr * 68 + o] = fmaxf(acc, 0.f);
    }
    __syncthreads();

    if (tid < 32) {
        int rr = tid >> 1, c = tid & 1;
        const float* hp = h1s + rr * 68;
        const float* wp = w2s + c * 64;
        float acc = b2s[c];
        #pragma unroll 8
        for (int k = 0; k < 64; k++) acc = fmaf(hp[k], wp[k], acc);
        float pred = softp(acc);
        int row = row0 + rr;
        if (mode == 0) {
            int t = row >> 10, b = row & 1023;
            if (t < 127) {
                long off = (long)b * 254 + t * 2 + c;
                #pragma unroll
                for (int s = 0; s < SS; s++)
                    outb[(long)s * ENC_SSTRIDE + off] = pred;
            } else {
                glast[b * 2 + c] = pred;
                #pragma unroll
                for (int s = 0; s < SS; s++)
                    outb[DEC_BASE + (long)((s << 10) | b) * 128 + c] = pred;
            }
        } else {
            dout[row * 2 + c] = pred;
            outb[DEC_BASE + (long)row * 128 + tstep * 2 + c] = pred;
        }
    }
}

// ---------------------------------------------------------------------------
// Reparameterization + decoder initial hidden states
// ---------------------------------------------------------------------------
__global__ void k_z(
    const float* __restrict__ hf0, const float* __restrict__ hf1,
    const float* __restrict__ eps, const float* __restrict__ feat,
    float* __restrict__ dh0, float* __restrict__ dh1)
{
    int idx = blockIdx.x * blockDim.x + threadIdx.x;
    if (idx >= SB * HD) return;
    int row = idx / HD, j = idx - row * HD;
    int s = row >> 10, b = row & 1023;
    float v0, v1;
    if (j < HH) {
        float m0 = hf0[b * HE + j],  lv0 = hf0[b * HE + HH + j];
        float m1 = hf1[b * HE + j],  lv1 = hf1[b * HE + HH + j];
        float e0 = eps[(((long)(s * 2 + 0) * BB + b) * HH) + j];
        float e1 = eps[(((long)(s * 2 + 1) * BB + b) * HH) + j];
        v0 = e0 * expf(0.5f * lv0) + m0;
        v1 = e1 * expf(0.5f * lv1) + m1;
    } else {
        float fc = feat[((long)b * TT + TENC) * FF + (j - HH)];
        v0 = fc; v1 = fc;
    }
    dh0[idx] = v0;
    dh1[idx] = v1;
}

__global__ void k_bcast_last(const float* __restrict__ last, float* __restrict__ dout)
{
    int i = blockIdx.x * blockDim.x + threadIdx.x;
    if (i < SB * 2) {
        int row = i >> 1, c = i & 1;
        dout[i] = last[((row & 1023) << 1) | c];
    }
}

__global__ void k_zero2(float* a, float* b, int n)
{
    int i = blockIdx.x * blockDim.x + threadIdx.x;
    if (i < n) { a[i] = 0.f; b[i] = 0.f; }
}

// ---------------------------------------------------------------------------
// Host orchestration (single stream, graph-capturable)
// ---------------------------------------------------------------------------
extern "C" void kernel_launch(void* const* d_in, const int* in_sizes, int n_in,
                              void* d_out, int out_size)
{
    const float* x    = (const float*)d_in[0];
    const float* feat = (const float*)d_in[1];
    const int*   mask = (const int*)d_in[2];
    const float* eps  = (const float*)d_in[3];

    int base = (n_in > 7 && in_sizes[4] == 1) ? 7 : 4;
    const float* eWih0 = (const float*)d_in[base + 0];
    const float* eWhh0 = (const float*)d_in[base + 1];
    const float* ebih0 = (const float*)d_in[base + 2];
    const float* ebhh0 = (const float*)d_in[base + 3];
    const float* eWih1 = (const float*)d_in[base + 4];
    const float* eWhh1 = (const float*)d_in[base + 5];
    const float* ebih1 = (const float*)d_in[base + 6];
    const float* ebhh1 = (const float*)d_in[base + 7];
    const float* dWih0 = (const float*)d_in[base + 8];
    const float* dWhh0 = (const float*)d_in[base + 9];
    const float* dbih0 = (const float*)d_in[base + 10];
    const float* dbhh0 = (const float*)d_in[base + 11];
    const float* dWih1 = (const float*)d_in[base + 12];
    const float* dWhh1 = (const float*)d_in[base + 13];
    const float* dbih1 = (const float*)d_in[base + 14];
    const float* dbhh1 = (const float*)d_in[base + 15];
    const float* W1    = (const float*)d_in[base + 16];
    const float* b1    = (const float*)d_in[base + 17];
    const float* W2    = (const float*)d_in[base + 18];
    const float* b2    = (const float*)d_in[base + 19];

    float* outb = (float*)d_out;

    float *p_h0, *p_h1, *p_enc, *p_last, *p_dh0, *p_dh1, *p_dout;
    cudaGetSymbolAddress((void**)&p_h0,   g_h0);
    cudaGetSymbolAddress((void**)&p_h1,   g_h1);
    cudaGetSymbolAddress((void**)&p_enc,  g_enc);
    cudaGetSymbolAddress((void**)&p_last, g_last);
    cudaGetSymbolAddress((void**)&p_dh0,  g_dh0);
    cudaGetSymbolAddress((void**)&p_dh1,  g_dh1);
    cudaGetSymbolAddress((void**)&p_dout, g_dout);

    cudaFuncSetAttribute(k_gru, cudaFuncAttributeMaxDynamicSharedMemorySize, SM_BYTES);
    cudaFuncSetAttribute(k_enc_step, cudaFuncAttributeMaxDynamicSharedMemorySize, SM_BYTES);

    const int HSZ = BB * HE;
    const int DSZ = SB * HD;
    float* X[2] = {p_h0, p_h0 + HSZ};
    float* Y[2] = {p_h1, p_h1 + HSZ};

    k_zero2<<<(HSZ + 255) / 256, 256>>>(p_h0, p_h1, HSZ);

    // ---------------- encoder: fused l0(t+1)+l1(t) chain ----------------
    dim3 eg0(BB / 32, 8);
    k_gru<<<eg0, 256, SM_BYTES>>>(X[0], X[1],
        x, 2, (long)TENC * 2, feat, FF, (long)TT * FF,
        eWih0, eWhh0, ebih0, ebhh0, mask, TENC, (float*)nullptr, HE);
    dim3 egf(BB / 32, 16);
    for (int t = 0; t < TENC; t++) {
        k_enc_step<<<egf, 256, SM_BYTES>>>(
            X[(t + 1) & 1], X[t & 1], Y[t & 1], Y[(t + 1) & 1],
            x, feat, mask, t, (t + 1 < TENC) ? 1 : 0,
            eWih0, eWhh0, ebih0, ebhh0,
            eWih1, eWhh1, ebih1, ebhh1, p_enc);
    }

    // ---------------- reparameterize + encoder MLP ----------------
    k_z<<<(SB * HD + 255) / 256, 256>>>(X[0], Y[0], eps, feat, p_dh0, p_dh1);
    k_mlp<<<(TENC * BB) / 16, 256>>>(p_enc, HH, W1, b1, W2, b2,
                                     outb, (float*)nullptr, p_last, 0, 0);
    k_bcast_last<<<(SB * 2 + 255) / 256, 256>>>(p_last, p_dout);

    // ---------------- decoder scan (R11 three-kernel flow) ----------------
    float* d0c = p_dh0;       float* d0n = p_dh0 + DSZ;
    float* d1c = p_dh1;       float* d1n = p_dh1 + DSZ;
    dim3 dgrid(SB / 32, (HD + 31) / 32);   // (256, 5)
    for (int t = 1; t < TDEC; t++) {
        k_gru<<<dgrid, 256, SM_BYTES>>>(d0c, d0n,
                              p_dout, 2, 2L,
                              (const float*)nullptr, 0, 0L,
                              dWih0, dWhh0, dbih0, dbhh0,
                              (const int*)nullptr, 0, (float*)nullptr, HD);
        k_gru<<<dgrid, 256, SM_BYTES>>>(d1c, d1n,
                              d0n, HD, (long)HD,
                              (const float*)nullptr, 0, 0L,
                              dWih1, dWhh1, dbih1, dbhh1,
                              (const int*)nullptr, 0, (float*)nullptr, HD);
        k_mlp<<<SB / 16, 256>>>(d1n, HD, W1, b1, W2, b2,
                                outb, p_dout, (float*)nullptr, 1, t);
        float* tmp;
        tmp = d0c; d0c = d0n; d0n = tmp;
        tmp = d1c; d1c = d1n; d1n = tmp;
    }
}

// round 16
// speedup vs baseline: 2.0507x; 1.0484x over previous
#include <cuda_runtime.h>
#include <cuda_bf16.h>
#include <math.h>

// ---------------------------------------------------------------------------
// Problem constants
// ---------------------------------------------------------------------------
#define BB    1024
#define TENC  128
#define TDEC  64
#define HH    128
#define FF    16
#define SS    8
#define HE    256
#define HD    132
#define SB    (SS*BB)
#define TT    (TENC+TDEC)
#define DEC_BASE 2080768    // 8*1024*127*2
#define ENC_SSTRIDE 260096  // 1024*127*2

typedef unsigned long long ull;

// ---------------------------------------------------------------------------
// Device scratch
// ---------------------------------------------------------------------------
__device__ __align__(128) float g_h0[2 * BB * HE];
__device__ __align__(128) float g_h1[2 * BB * HE];
__device__ __align__(128) float g_enc[TENC * BB * HH];
__device__ __align__(128) float g_last[BB * 2];
__device__ __align__(128) float g_dh0[2 * SB * HD];
__device__ __align__(128) float g_dh1[2 * SB * HD];
__device__ __align__(128) float g_dout[SB * 2];

// ---------------------------------------------------------------------------
// Helpers
// ---------------------------------------------------------------------------
__device__ __forceinline__ float sigm(float x)  { return 1.f / (1.f + __expf(-x)); }
__device__ __forceinline__ float tanhff(float x){ return 2.f / (1.f + __expf(-2.f * x)) - 1.f; }
__device__ __forceinline__ float softp(float x) {
    return fmaxf(x, 0.f) + log1pf(expf(-fabsf(x)));
}
__device__ __forceinline__ void fma2(ull &d, ull a, ull b) {
    asm("fma.rn.f32x2 %0, %1, %2, %0;" : "+l"(d) : "l"(a), "l"(b));
}
__device__ __forceinline__ float hsum2(ull v) {
    float lo = __uint_as_float((unsigned)(v & 0xffffffffull));
    float hi = __uint_as_float((unsigned)(v >> 32));
    return lo + hi;
}
__device__ __forceinline__ void cpa16(float* dst, const float* src) {
    unsigned sa = (unsigned)__cvta_generic_to_shared(dst);
    asm volatile("cp.async.cg.shared.global [%0], [%1], 16;\n" :: "r"(sa), "l"(src));
}
__device__ __forceinline__ void cpa_commit() { asm volatile("cp.async.commit_group;\n"); }
template<int N> __device__ __forceinline__ void cpa_wait() {
    asm volatile("cp.async.wait_group %0;\n" :: "n"(N));
}

// Chunking: chunks of 64, except a final chunk of up to 68 (buffer row = 68).
__device__ __forceinline__ int nchunks(int kdim) {
    return (kdim <= 68) ? 1 : ((kdim + 59) >> 6);
}

// buffer layout per chunk: [ h: 32 rows x 68 | w: 96 rows x 68 ], double buffered
#define TRR    32
#define RT     4
#define SM_HW  (TRR * 68)
#define SM_BUF (TRR * 68 + 96 * 68)
#define SM_BYTES (2 * SM_BUF * 4)          // 69632

// ---------------------------------------------------------------------------
// Stage one K-chunk (width W floats, W % 4 == 0, W <= 68) of activations
// (32 rows) + weights (3 x nv valid rows) via cp.async. Rows for invalid
// units (j >= whid) are NOT staged: dead lanes compute garbage that is
// never stored (epilogue guards j < hid).
// ---------------------------------------------------------------------------
__device__ __forceinline__ void stage_chunk(
    float* buf,
    const float* __restrict__ act, long actStride,
    const float* __restrict__ W, int wstride, int whid,
    int jt0, int rb0, int kc, int width, int nv, int tid)
{
    float* hbuf = buf;
    float* wbuf = buf + SM_HW;
    if (width == 64 && nv == 32) {
        for (int idx = tid; idx < 2048; idx += 256) {
            if (idx < 512) {
                int r = idx >> 4, q = idx & 15;
                cpa16(hbuf + r * 68 + q * 4,
                      act + (long)(rb0 + r) * actStride + kc + q * 4);
            } else {
                int wv = idx - 512;
                int rr = wv >> 4, q = wv & 15;
                cpa16(wbuf + rr * 68 + q * 4,
                      W + ((long)(rr >> 5) * whid + jt0 + (rr & 31)) * wstride
                        + kc + q * 4);
            }
        }
    } else {
        int wq = width >> 2;           // float4s per row (<= 17)
        int nh = TRR * wq;
        int nw = 3 * nv * wq;
        for (int idx = tid; idx < nh + nw; idx += 256) {
            if (idx < nh) {
                int r = idx / wq, q = idx - r * wq;
                cpa16(hbuf + r * 68 + q * 4,
                      act + (long)(rb0 + r) * actStride + kc + q * 4);
            } else {
                int wv = idx - nh;
                int rr = wv / wq, q = wv - rr * wq;
                int g = rr / nv, jj = rr - g * nv;
                cpa16(wbuf + (g * 32 + jj) * 68 + q * 4,
                      W + ((long)g * whid + jt0 + jj) * wstride + kc + q * 4);
            }
        }
    }
}

// ---------------------------------------------------------------------------
// Compute one staged chunk: 4 rows x (r,z,n) per thread, packed f32x2.
// ---------------------------------------------------------------------------
__device__ __forceinline__ void compute_chunk(
    const float* hb, const float* wr, const float* wz, const float* wn,
    int klim, ull* aR, ull* aZ, ull* aN)
{
#define CK_BODY(k) { \
    ulonglong2 r2 = *(const ulonglong2*)(wr + (k)); \
    ulonglong2 z2 = *(const ulonglong2*)(wz + (k)); \
    ulonglong2 n2 = *(const ulonglong2*)(wn + (k)); \
    _Pragma("unroll") \
    for (int i = 0; i < RT; i++) { \
        ulonglong2 h2 = *(const ulonglong2*)(hb + i * 68 + (k)); \
        fma2(aR[i], h2.x, r2.x); fma2(aR[i], h2.y, r2.y); \
        fma2(aZ[i], h2.x, z2.x); fma2(aZ[i], h2.y, z2.y); \
        fma2(aN[i], h2.x, n2.x); fma2(aN[i], h2.y, n2.y); \
    } }
    if (klim == 64) {
        #pragma unroll 8
        for (int k = 0; k < 64; k += 4) CK_BODY(k)
    } else {
        for (int k = 0; k < klim; k += 4) CK_BODY(k)
    }
#undef CK_BODY
}

// ---------------------------------------------------------------------------
// Fused hidden+input accumulation: continuous double-buffered pipeline.
// ---------------------------------------------------------------------------
struct ChunkP { const float* act; long stride; const float* W; int wstr;
                int base; int width; int isH; };

__device__ __forceinline__ void chunk_params(
    int c, int nH, int hid,
    const float* actH, const float* WH,
    const float* actA, long strideA, int kA,
    const float* WA, int wstrideA, ChunkP& p)
{
    if (c < nH) {
        p.act = actH; p.stride = hid; p.W = WH; p.wstr = hid;
        p.base = c * 64;
        p.width = (c == nH - 1) ? (hid - p.base) : 64;
        p.isH = 1;
    } else {
        int cc = c - nH;
        int nA = nchunks(kA);
        p.act = actA; p.stride = strideA; p.W = WA; p.wstr = wstrideA;
        p.base = cc * 64;
        p.width = (cc == nA - 1) ? (kA - p.base) : 64;
        p.isH = 0;
    }
}

__device__ __forceinline__ void accum_dual(
    float* sm, int whid, int nv,
    const float* __restrict__ actH, int hid, const float* __restrict__ WH,
    const float* __restrict__ actA, long strideA, int kA,
    const float* __restrict__ WA, int wstrideA,
    int jt0, int rb0, int tid, int lane, int warp,
    ull* aR, ull* aZ, ull* aNh, ull* aNi)
{
    int nH = nchunks(hid);
    int nA = (kA > 0) ? nchunks(kA) : 0;
    int nch = nH + nA;

    ChunkP p;
    chunk_params(0, nH, hid, actH, WH, actA, strideA, kA, WA, wstrideA, p);
    stage_chunk(sm, p.act, p.stride, p.W, p.wstr, whid, jt0, rb0,
                p.base, p.width, nv, tid);
    cpa_commit();
    for (int c = 0; c < nch; c++) {
        float* cur = sm + (c & 1) * SM_BUF;
        chunk_params(c, nH, hid, actH, WH, actA, strideA, kA, WA, wstrideA, p);
        if (c + 1 < nch) {
            ChunkP pn;
            chunk_params(c + 1, nH, hid, actH, WH, actA, strideA, kA, WA, wstrideA, pn);
            stage_chunk(sm + ((c + 1) & 1) * SM_BUF, pn.act, pn.stride,
                        pn.W, pn.wstr, whid, jt0, rb0, pn.base, pn.width, nv, tid);
            cpa_commit();
            cpa_wait<1>();
        } else {
            cpa_wait<0>();
        }
        __syncthreads();
        ull* aN = p.isH ? aNh : aNi;
        compute_chunk(cur + warp * RT * 68,
                      cur + SM_HW + lane * 68,
                      cur + SM_HW + (32 + lane) * 68,
                      cur + SM_HW + (64 + lane) * 68,
                      p.width, aR, aZ, aN);
        __syncthreads();
    }
}

// Direct gmem pass for small input dims (<=32): no staging, scalar fp32.
__device__ __forceinline__ void accum_direct(
    const float* __restrict__ act, long actStride, int kdim,
    const float* __restrict__ W, int wstride, int whid,
    int j, int row0, float* gR, float* gZ, float* gN)
{
    if (j >= whid) return;
    for (int k = 0; k < kdim; k++) {
        float wr = W[(long)j * wstride + k];
        float wz = W[((long)whid + j) * wstride + k];
        float wn = W[((long)2 * whid + j) * wstride + k];
        #pragma unroll
        for (int i = 0; i < RT; i++) {
            float xv = act[(long)(row0 + i) * actStride + k];
            gR[i] = fmaf(xv, wr, gR[i]);
            gZ[i] = fmaf(xv, wz, gZ[i]);
            gN[i] = fmaf(xv, wn, gN[i]);
        }
    }
}

// ---------------------------------------------------------------------------
// GRU tile body: 32 rows x 32 units, 256 threads.
// ---------------------------------------------------------------------------
__device__ __forceinline__ void gru_tile(
    float* sm,
    const float* __restrict__ Hprev, float* __restrict__ Hnext,
    const float* __restrict__ XA, int dimA, long strideA,
    const float* __restrict__ XB, int dimB, long strideB,
    const float* __restrict__ Wih, const float* __restrict__ Whh,
    const float* __restrict__ bih, const float* __restrict__ bhh,
    const int* __restrict__ mask, int maskStride,
    float* __restrict__ mOut, int hid,
    int rb0, int jt0)
{
    int tid = threadIdx.x, lane = tid & 31, warp = tid >> 5;
    int j = jt0 + lane;
    int row0 = rb0 + warp * RT;
    int in_dim = dimA + dimB;
    int nv = hid - jt0; if (nv > 32) nv = 32;

    // prefetch epilogue operands (latency hidden under GEMM)
    float hold[RT];
    int mv[RT];
    #pragma unroll
    for (int i = 0; i < RT; i++) {
        hold[i] = (j < hid) ? Hprev[(long)(row0 + i) * hid + j] : 0.f;
        mv[i] = mask ? mask[(long)(row0 + i) * maskStride] : 1;
    }

    ull aR[RT], aZ[RT], aNh[RT], aNi[RT];
    float gR[RT], gZ[RT], gN[RT];
    #pragma unroll
    for (int i = 0; i < RT; i++) {
        aR[i] = 0; aZ[i] = 0; aNh[i] = 0; aNi[i] = 0;
        gR[i] = 0.f; gZ[i] = 0.f; gN[i] = 0.f;
    }

    if (dimA > 32) {
        accum_dual(sm, hid, nv, Hprev, hid, Whh, XA, strideA, dimA, Wih, in_dim,
                   jt0, rb0, tid, lane, warp, aR, aZ, aNh, aNi);
    } else {
        accum_dual(sm, hid, nv, Hprev, hid, Whh,
                   (const float*)nullptr, 0L, 0, (const float*)nullptr, 0,
                   jt0, rb0, tid, lane, warp, aR, aZ, aNh, aNi);
        if (dimA > 0)
            accum_direct(XA, strideA, dimA, Wih, in_dim, hid,
                         j, row0, gR, gZ, gN);
    }
    if (dimB > 0)
        accum_direct(XB, strideB, dimB, Wih + dimA, in_dim, hid,
                     j, row0, gR, gZ, gN);

    if (j >= hid) return;

    float bR  = bih[j] + bhh[j];
    float bZ  = bih[hid + j] + bhh[hid + j];
    float bNi = bih[2 * hid + j];
    float bNh = bhh[2 * hid + j];
    #pragma unroll
    for (int i = 0; i < RT; i++) {
        int row = row0 + i;
        float r = sigm(hsum2(aR[i]) + gR[i] + bR);
        float z = sigm(hsum2(aZ[i]) + gZ[i] + bZ);
        float n = tanhff(hsum2(aNi[i]) + gN[i] + bNi + r * (hsum2(aNh[i]) + bNh));
        float hn = (1.f - z) * n + z * hold[i];
        float hf = mv[i] ? hn : hold[i];
        Hnext[(long)row * hid + j] = hf;
        if (mOut && j < HH)
            mOut[(long)row * HH + j] = mv[i] ? hf : 0.f;
    }
}

// ---------------------------------------------------------------------------
// Generic GRU step kernel (enc l0(0), decoder layers). 2 CTAs/SM.
// ---------------------------------------------------------------------------
__global__ __launch_bounds__(256, 2) void k_gru(
    const float* __restrict__ Hprev, float* __restrict__ Hnext,
    const float* __restrict__ XA, int dimA, long strideA,
    const float* __restrict__ XB, int dimB, long strideB,
    const float* __restrict__ Wih, const float* __restrict__ Whh,
    const float* __restrict__ bih, const float* __restrict__ bhh,
    const int* __restrict__ mask, int maskStride,
    float* __restrict__ mOut, int hid)
{
    extern __shared__ __align__(16) float sm[];
    gru_tile(sm, Hprev, Hnext, XA, dimA, strideA, XB, dimB, strideB,
             Wih, Whh, bih, bhh, mask, maskStride, mOut, hid,
             blockIdx.x * TRR, blockIdx.y * 32);
}

// ---------------------------------------------------------------------------
// Fused encoder step: one launch computes l0(t+1) AND l1(t) (independent).
// grid = (32, 16): y<8 -> l0(t+1), y>=8 -> l1(t). 2 CTAs/SM (regs=128, no spill).
// ---------------------------------------------------------------------------
__global__ __launch_bounds__(256, 2) void k_enc_step(
    const float* __restrict__ Xin, float* __restrict__ Xout,
    const float* __restrict__ Yin, float* __restrict__ Yout,
    const float* __restrict__ x, const float* __restrict__ feat,
    const int* __restrict__ mask, int t, int do_l0,
    const float* __restrict__ eWih0, const float* __restrict__ eWhh0,
    const float* __restrict__ ebih0, const float* __restrict__ ebhh0,
    const float* __restrict__ eWih1, const float* __restrict__ eWhh1,
    const float* __restrict__ ebih1, const float* __restrict__ ebhh1,
    float* __restrict__ encout)
{
    extern __shared__ __align__(16) float sm[];
    int rb0 = blockIdx.x * TRR;
    if (blockIdx.y < 8) {
        if (!do_l0) return;
        int tn = t + 1;
        gru_tile(sm, Xin, Xout,
                 x + (long)tn * 2, 2, (long)TENC * 2,
                 feat + (long)tn * FF, FF, (long)TT * FF,
                 eWih0, eWhh0, ebih0, ebhh0,
                 mask + tn, TENC, (float*)nullptr, HE,
                 rb0, blockIdx.y * 32);
    } else {
        gru_tile(sm, Yin, Yout,
                 Xin, HE, (long)HE,
                 (const float*)nullptr, 0, 0L,
                 eWih1, eWhh1, ebih1, ebhh1,
                 mask + t, TENC,
                 encout + (long)t * BB * HH, HE,
                 rb0, (blockIdx.y - 8) * 32);
    }
}

// ---------------------------------------------------------------------------
// MLP: softplus(relu(h @ W1^T + b1) @ W2^T + b2), 16 rows per block.
// ---------------------------------------------------------------------------
__global__ __launch_bounds__(256) void k_mlp(
    const float* __restrict__ Hin, int hstride,
    const float* __restrict__ W1, const float* __restrict__ b1,
    const float* __restrict__ W2, const float* __restrict__ b2,
    float* __restrict__ outb, float* __restrict__ dout,
    float* __restrict__ glast, int mode, int tstep)
{
    __shared__ __align__(16) float w1s[64 * 132];
    __shared__ __align__(16) float hs[16 * 132];
    __shared__ float h1s[16 * 68];
    __shared__ float w2s[128];
    __shared__ float b1s[64];
    __shared__ float b2s[2];

    int tid = threadIdx.x;
    int row0 = blockIdx.x * 16;

    for (int idx = tid; idx < 64 * 128; idx += 256) {
        int o = idx >> 7, k = idx & 127;
        w1s[o * 132 + k] = W1[idx];
    }
    for (int idx = tid; idx < 16 * 128; idx += 256) {
        int rr = idx >> 7, k = idx & 127;
        hs[rr * 132 + k] = Hin[(long)(row0 + rr) * hstride + k];
    }
    if (tid < 128) w2s[tid] = W2[tid];
    if (tid < 64)  b1s[tid] = b1[tid];
    if (tid < 2)   b2s[tid] = b2[tid];
    __syncthreads();

    #pragma unroll
    for (int p = 0; p < 4; p++) {
        int idx = p * 256 + tid;
        int o = idx & 63, rr = idx >> 6;
        const float* wp = w1s + o * 132;
        const float* hp = hs + rr * 132;
        float acc = b1s[o];
        #pragma unroll 8
        for (int k = 0; k < 128; k += 4) {
            float4 w4 = *(const float4*)(wp + k);
            float4 h4 = *(const float4*)(hp + k);
            acc = fmaf(w4.x, h4.x, acc);
            acc = fmaf(w4.y, h4.y, acc);
            acc = fmaf(w4.z, h4.z, acc);
            acc = fmaf(w4.w, h4.w, acc);
        }
        h1s[rr * 68 + o] = fmaxf(acc, 0.f);
    }
    __syncthreads();

    if (tid < 32) {
        int rr = tid >> 1, c = tid & 1;
        const float* hp = h1s + rr * 68;
        const float* wp = w2s + c * 64;
        float acc = b2s[c];
        #pragma unroll 8
        for (int k = 0; k < 64; k++) acc = fmaf(hp[k], wp[k], acc);
        float pred = softp(acc);
        int row = row0 + rr;
        if (mode == 0) {
            int t = row >> 10, b = row & 1023;
            if (t < 127) {
                long off = (long)b * 254 + t * 2 + c;
                #pragma unroll
                for (int s = 0; s < SS; s++)
                    outb[(long)s * ENC_SSTRIDE + off] = pred;
            } else {
                glast[b * 2 + c] = pred;
                #pragma unroll
                for (int s = 0; s < SS; s++)
                    outb[DEC_BASE + (long)((s << 10) | b) * 128 + c] = pred;
            }
        } else {
            dout[row * 2 + c] = pred;
            outb[DEC_BASE + (long)row * 128 + tstep * 2 + c] = pred;
        }
    }
}

// ---------------------------------------------------------------------------
// Reparameterization + decoder initial hidden states
// ---------------------------------------------------------------------------
__global__ void k_z(
    const float* __restrict__ hf0, const float* __restrict__ hf1,
    const float* __restrict__ eps, const float* __restrict__ feat,
    float* __restrict__ dh0, float* __restrict__ dh1)
{
    int idx = blockIdx.x * blockDim.x + threadIdx.x;
    if (idx >= SB * HD) return;
    int row = idx / HD, j = idx - row * HD;
    int s = row >> 10, b = row & 1023;
    float v0, v1;
    if (j < HH) {
        float m0 = hf0[b * HE + j],  lv0 = hf0[b * HE + HH + j];
        float m1 = hf1[b * HE + j],  lv1 = hf1[b * HE + HH + j];
        float e0 = eps[(((long)(s * 2 + 0) * BB + b) * HH) + j];
        float e1 = eps[(((long)(s * 2 + 1) * BB + b) * HH) + j];
        v0 = e0 * expf(0.5f * lv0) + m0;
        v1 = e1 * expf(0.5f * lv1) + m1;
    } else {
        float fc = feat[((long)b * TT + TENC) * FF + (j - HH)];
        v0 = fc; v1 = fc;
    }
    dh0[idx] = v0;
    dh1[idx] = v1;
}

__global__ void k_bcast_last(const float* __restrict__ last, float* __restrict__ dout)
{
    int i = blockIdx.x * blockDim.x + threadIdx.x;
    if (i < SB * 2) {
        int row = i >> 1, c = i & 1;
        dout[i] = last[((row & 1023) << 1) | c];
    }
}

__global__ void k_zero2(float* a, float* b, int n)
{
    int i = blockIdx.x * blockDim.x + threadIdx.x;
    if (i < n) { a[i] = 0.f; b[i] = 0.f; }
}

// ---------------------------------------------------------------------------
// Host orchestration (single stream, graph-capturable)
// ---------------------------------------------------------------------------
extern "C" void kernel_launch(void* const* d_in, const int* in_sizes, int n_in,
                              void* d_out, int out_size)
{
    const float* x    = (const float*)d_in[0];
    const float* feat = (const float*)d_in[1];
    const int*   mask = (const int*)d_in[2];
    const float* eps  = (const float*)d_in[3];

    int base = (n_in > 7 && in_sizes[4] == 1) ? 7 : 4;
    const float* eWih0 = (const float*)d_in[base + 0];
    const float* eWhh0 = (const float*)d_in[base + 1];
    const float* ebih0 = (const float*)d_in[base + 2];
    const float* ebhh0 = (const float*)d_in[base + 3];
    const float* eWih1 = (const float*)d_in[base + 4];
    const float* eWhh1 = (const float*)d_in[base + 5];
    const float* ebih1 = (const float*)d_in[base + 6];
    const float* ebhh1 = (const float*)d_in[base + 7];
    const float* dWih0 = (const float*)d_in[base + 8];
    const float* dWhh0 = (const float*)d_in[base + 9];
    const float* dbih0 = (const float*)d_in[base + 10];
    const float* dbhh0 = (const float*)d_in[base + 11];
    const float* dWih1 = (const float*)d_in[base + 12];
    const float* dWhh1 = (const float*)d_in[base + 13];
    const float* dbih1 = (const float*)d_in[base + 14];
    const float* dbhh1 = (const float*)d_in[base + 15];
    const float* W1    = (const float*)d_in[base + 16];
    const float* b1    = (const float*)d_in[base + 17];
    const float* W2    = (const float*)d_in[base + 18];
    const float* b2    = (const float*)d_in[base + 19];

    float* outb = (float*)d_out;

    float *p_h0, *p_h1, *p_enc, *p_last, *p_dh0, *p_dh1, *p_dout;
    cudaGetSymbolAddress((void**)&p_h0,   g_h0);
    cudaGetSymbolAddress((void**)&p_h1,   g_h1);
    cudaGetSymbolAddress((void**)&p_enc,  g_enc);
    cudaGetSymbolAddress((void**)&p_last, g_last);
    cudaGetSymbolAddress((void**)&p_dh0,  g_dh0);
    cudaGetSymbolAddress((void**)&p_dh1,  g_dh1);
    cudaGetSymbolAddress((void**)&p_dout, g_dout);

    cudaFuncSetAttribute(k_gru, cudaFuncAttributeMaxDynamicSharedMemorySize, SM_BYTES);
    cudaFuncSetAttribute(k_enc_step, cudaFuncAttributeMaxDynamicSharedMemorySize, SM_BYTES);

    const int HSZ = BB * HE;
    const int DSZ = SB * HD;
    float* X[2] = {p_h0, p_h0 + HSZ};
    float* Y[2] = {p_h1, p_h1 + HSZ};

    k_zero2<<<(HSZ + 255) / 256, 256>>>(p_h0, p_h1, HSZ);

    // ---------------- encoder: fused l0(t+1)+l1(t) chain ----------------
    dim3 eg0(BB / 32, 8);
    k_gru<<<eg0, 256, SM_BYTES>>>(X[0], X[1],
        x, 2, (long)TENC * 2, feat, FF, (long)TT * FF,
        eWih0, eWhh0, ebih0, ebhh0, mask, TENC, (float*)nullptr, HE);
    dim3 egf(BB / 32, 16);
    for (int t = 0; t < TENC; t++) {
        k_enc_step<<<egf, 256, SM_BYTES>>>(
            X[(t + 1) & 1], X[t & 1], Y[t & 1], Y[(t + 1) & 1],
            x, feat, mask, t, (t + 1 < TENC) ? 1 : 0,
            eWih0, eWhh0, ebih0, ebhh0,
            eWih1, eWhh1, ebih1, ebhh1, p_enc);
    }

    // ---------------- reparameterize + encoder MLP ----------------
    k_z<<<(SB * HD + 255) / 256, 256>>>(X[0], Y[0], eps, feat, p_dh0, p_dh1);
    k_mlp<<<(TENC * BB) / 16, 256>>>(p_enc, HH, W1, b1, W2, b2,
                                     outb, (float*)nullptr, p_last, 0, 0);
    k_bcast_last<<<(SB * 2 + 255) / 256, 256>>>(p_last, p_dout);

    // ---------------- decoder scan (R11 three-kernel flow) ----------------
    float* d0c = p_dh0;       float* d0n = p_dh0 + DSZ;
    float* d1c = p_dh1;       float* d1n = p_dh1 + DSZ;
    dim3 dgrid(SB / 32, (HD + 31) / 32);   // (256, 5)
    for (int t = 1; t < TDEC; t++) {
        k_gru<<<dgrid, 256, SM_BYTES>>>(d0c, d0n,
                              p_dout, 2, 2L,
                              (const float*)nullptr, 0, 0L,
                              dWih0, dWhh0, dbih0, dbhh0,
                              (const int*)nullptr, 0, (float*)nullptr, HD);
        k_gru<<<dgrid, 256, SM_BYTES>>>(d1c, d1n,
                              d0n, HD, (long)HD,
                              (const float*)nullptr, 0, 0L,
                              dWih1, dWhh1, dbih1, dbhh1,
                              (const int*)nullptr, 0, (float*)nullptr, HD);
        k_mlp<<<SB / 16, 256>>>(d1n, HD, W1, b1, W2, b2,
                                outb, p_dout, (float*)nullptr, 1, t);
        float* tmp;
        tmp = d0c; d0c = d0n; d0n = tmp;
        tmp = d1c; d1c = d1n; d1n = tmp;
    }
}